// round 4
// baseline (speedup 1.0000x reference)
#include <cuda_runtime.h>
#include <math.h>

#define NN 50000
#define NE 800000
#define DD 64
#define NR 500
#define NT 1000
#define NB_SCAN ((NN + 255) / 256)   // 196

// ---- scratch (no allocs allowed) ----
__device__ float g_hatt[NN];
__device__ float g_tatt[NN];
__device__ float g_ratt[NR];
__device__ float g_tsatt[NT];
__device__ int   g_cnt[NN];
__device__ int   g_off[NN + 1];
__device__ int   g_cur[NN];
__device__ int   g_bsum[NB_SCAN];
__device__ float g_sex[NE];          // ex, dst-sorted order
__device__ int2  g_sidx[NE];         // {src | ety<<17, eti}, dst-sorted
__device__ float g_agg[NN * DD];

// ---------------------------------------------------------------------------
// Zero histogram counters.
// ---------------------------------------------------------------------------
__global__ void k_zero() {
    int i = blockIdx.x * blockDim.x + threadIdx.x;
    if (i < NN) g_cnt[i] = 0;
}

// ---------------------------------------------------------------------------
// Per-row scalar attention projections: warp per row.
// ---------------------------------------------------------------------------
__global__ void k_scalar(const float* __restrict__ x,
                         const float* __restrict__ rel,
                         const float* __restrict__ tm,
                         const float* __restrict__ ah,
                         const float* __restrict__ at,
                         const float* __restrict__ ar,
                         const float* __restrict__ ats) {
    int w = (blockIdx.x * blockDim.x + threadIdx.x) >> 5;
    int lane = threadIdx.x & 31;
    if (w < NN) {
        const float* row = x + (size_t)w * DD;
        float v0 = row[lane], v1 = row[lane + 32];
        float h = v0 * ah[lane] + v1 * ah[lane + 32];
        float t = v0 * at[lane] + v1 * at[lane + 32];
#pragma unroll
        for (int o = 16; o; o >>= 1) {
            h += __shfl_xor_sync(0xffffffffu, h, o);
            t += __shfl_xor_sync(0xffffffffu, t, o);
        }
        if (lane == 0) { g_hatt[w] = h; g_tatt[w] = t; }
    } else if (w < NN + NR) {
        int r = w - NN;
        const float* row = rel + (size_t)r * DD;
        float s = row[lane] * ar[lane] + row[lane + 32] * ar[lane + 32];
#pragma unroll
        for (int o = 16; o; o >>= 1) s += __shfl_xor_sync(0xffffffffu, s, o);
        if (lane == 0) g_ratt[r] = s;
    } else if (w < NN + NR + NT) {
        int t = w - NN - NR;
        const float* row = tm + (size_t)t * DD;
        float s = row[lane] * ats[lane] + row[lane + 32] * ats[lane + 32];
#pragma unroll
        for (int o = 16; o; o >>= 1) s += __shfl_xor_sync(0xffffffffu, s, o);
        if (lane == 0) g_tsatt[t] = s;
    }
}

// ---------------------------------------------------------------------------
// Histogram of dst.
// ---------------------------------------------------------------------------
__global__ void k_hist(const int* __restrict__ dst) {
    int i = blockIdx.x * blockDim.x + threadIdx.x;
    if (i < NE) atomicAdd(&g_cnt[dst[i]], 1);
}

// ---------------------------------------------------------------------------
// 2-level exclusive scan of g_cnt -> g_off  (block-local pass).
// ---------------------------------------------------------------------------
__global__ void k_scan1() {
    __shared__ int wsum[8];
    int tid = threadIdx.x, lane = tid & 31, wid = tid >> 5;
    int i = blockIdx.x * 256 + tid;
    int v = (i < NN) ? g_cnt[i] : 0;
    int inc = v;
#pragma unroll
    for (int o = 1; o < 32; o <<= 1) {
        int n = __shfl_up_sync(0xffffffffu, inc, o);
        if (lane >= o) inc += n;
    }
    if (lane == 31) wsum[wid] = inc;
    __syncthreads();
    if (wid == 0) {
        int s = (lane < 8) ? wsum[lane] : 0;
#pragma unroll
        for (int o = 1; o < 8; o <<= 1) {
            int n = __shfl_up_sync(0xffffffffu, s, o);
            if (lane >= o) s += n;
        }
        if (lane < 8) wsum[lane] = s;
    }
    __syncthreads();
    int base = (wid > 0) ? wsum[wid - 1] : 0;
    if (i < NN) g_off[i] = base + inc - v;   // exclusive within block
    if (tid == 255) g_bsum[blockIdx.x] = base + inc;
}

// Scan the block sums (single block; NB_SCAN <= 256).
__global__ void k_scan2() {
    __shared__ int wsum[8];
    int tid = threadIdx.x, lane = tid & 31, wid = tid >> 5;
    int v = (tid < NB_SCAN) ? g_bsum[tid] : 0;
    int inc = v;
#pragma unroll
    for (int o = 1; o < 32; o <<= 1) {
        int n = __shfl_up_sync(0xffffffffu, inc, o);
        if (lane >= o) inc += n;
    }
    if (lane == 31) wsum[wid] = inc;
    __syncthreads();
    if (wid == 0) {
        int s = (lane < 8) ? wsum[lane] : 0;
#pragma unroll
        for (int o = 1; o < 8; o <<= 1) {
            int n = __shfl_up_sync(0xffffffffu, s, o);
            if (lane >= o) s += n;
        }
        if (lane < 8) wsum[lane] = s;
    }
    __syncthreads();
    int base = (wid > 0) ? wsum[wid - 1] : 0;
    if (tid < NB_SCAN) g_bsum[tid] = base + inc - v;   // exclusive block offsets
}

// Add block offsets; init cursor copy; set sentinel.
__global__ void k_scan3() {
    int i = blockIdx.x * blockDim.x + threadIdx.x;
    if (i < NN) {
        int o = g_off[i] + g_bsum[i >> 8];
        g_off[i] = o;
        g_cur[i] = o;
    }
    if (i == 0) g_off[NN] = NE;
}

// ---------------------------------------------------------------------------
// Edge pass 1: ex = exp(leaky_relu(logit)); scatter edge into dst-sorted slot.
// ---------------------------------------------------------------------------
__global__ void k_edge1(const int* __restrict__ src, const int* __restrict__ dst,
                        const int* __restrict__ ety, const int* __restrict__ eti) {
    int i = blockIdx.x * blockDim.x + threadIdx.x;
    if (i >= NE) return;
    int s = src[i], d = dst[i], r = ety[i], t = eti[i];
    float e = g_hatt[s] - g_tatt[d] + g_ratt[r] + g_tsatt[t];
    e = (e > 0.f) ? e : 0.1f * e;
    float ex = __expf(e);
    int pos = atomicAdd(&g_cur[d], 1);
    g_sex[pos] = ex;
    g_sidx[pos] = make_int2(s | (r << 17), t);
}

// ---------------------------------------------------------------------------
// Aggregation: one warp per dst node. Lanes own cols {lane, lane+32}.
// agg[d] = (sum_e ex_e * (x[src]+t)*(r+t)) / (sum_e ex_e)
// ---------------------------------------------------------------------------
__global__ void k_agg(const float* __restrict__ x,
                      const float* __restrict__ rel,
                      const float* __restrict__ tm) {
    int d = (blockIdx.x * blockDim.x + threadIdx.x) >> 5;
    if (d >= NN) return;
    int lane = threadIdx.x & 31;
    int beg = g_off[d], end = g_off[d + 1];

    float acc0 = 0.f, acc1 = 0.f, dsum = 0.f;
#pragma unroll 2
    for (int e = beg; e < end; ++e) {
        int2 pk = __ldg(&g_sidx[e]);       // broadcast
        float ex = __ldg(&g_sex[e]);       // broadcast
        int s = pk.x & 0x1FFFF;
        int r = ((unsigned)pk.x) >> 17;
        int t = pk.y;
        const float* xr = x   + (size_t)s * DD;
        const float* rr = rel + (size_t)r * DD;
        const float* tr = tm  + (size_t)t * DD;
        float xv0 = __ldg(xr + lane),      xv1 = __ldg(xr + lane + 32);
        float tv0 = __ldg(tr + lane),      tv1 = __ldg(tr + lane + 32);
        float rv0 = __ldg(rr + lane),      rv1 = __ldg(rr + lane + 32);
        acc0 += ex * (xv0 + tv0) * (rv0 + tv0);
        acc1 += ex * (xv1 + tv1) * (rv1 + tv1);
        dsum += ex;
    }
    float inv = (end > beg) ? __fdividef(1.f, dsum) : 0.f;
    g_agg[(size_t)d * DD + lane]      = acc0 * inv;
    g_agg[(size_t)d * DD + lane + 32] = acc1 * inv;
}

// ---------------------------------------------------------------------------
// x_out = agg @ trans_w + x @ loop_w   (64-row tile, 4x4 register tiles)
// ---------------------------------------------------------------------------
__global__ void k_gemm(const float* __restrict__ x,
                       const float* __restrict__ wt,
                       const float* __restrict__ wl,
                       float* __restrict__ out) {
    __shared__ __align__(16) float sWt[DD * DD];
    __shared__ __align__(16) float sWl[DD * DD];
    __shared__ float sA[64 * 65];
    __shared__ float sX[64 * 65];

    int tid = threadIdx.x;
    for (int j = tid; j < DD * DD; j += 256) { sWt[j] = wt[j]; sWl[j] = wl[j]; }

    int row0 = blockIdx.x * 64;
    {
        int r = tid >> 4;
        int c4 = (tid & 15) * 4;
        for (int rr = r; rr < 64; rr += 16) {
            int grow = row0 + rr;
            float4 a = make_float4(0.f, 0.f, 0.f, 0.f);
            float4 b = make_float4(0.f, 0.f, 0.f, 0.f);
            if (grow < NN) {
                a = *(const float4*)&g_agg[(size_t)grow * DD + c4];
                b = *(const float4*)(x + (size_t)grow * DD + c4);
            }
            float* pa = &sA[rr * 65 + c4];
            float* pb = &sX[rr * 65 + c4];
            pa[0] = a.x; pa[1] = a.y; pa[2] = a.z; pa[3] = a.w;
            pb[0] = b.x; pb[1] = b.y; pb[2] = b.z; pb[3] = b.w;
        }
    }
    __syncthreads();

    int tx = tid & 15;
    int ty = tid >> 4;
    float acc[4][4];
#pragma unroll
    for (int ri = 0; ri < 4; ri++)
#pragma unroll
        for (int cj = 0; cj < 4; cj++) acc[ri][cj] = 0.f;

#pragma unroll 4
    for (int k = 0; k < DD; k++) {
        float4 w0 = *(const float4*)&sWt[k * DD + tx * 4];
        float4 w1 = *(const float4*)&sWl[k * DD + tx * 4];
#pragma unroll
        for (int ri = 0; ri < 4; ri++) {
            float a = sA[(ty * 4 + ri) * 65 + k];
            float b = sX[(ty * 4 + ri) * 65 + k];
            acc[ri][0] += a * w0.x + b * w1.x;
            acc[ri][1] += a * w0.y + b * w1.y;
            acc[ri][2] += a * w0.z + b * w1.z;
            acc[ri][3] += a * w0.w + b * w1.w;
        }
    }

#pragma unroll
    for (int ri = 0; ri < 4; ri++) {
        int grow = row0 + ty * 4 + ri;
        if (grow < NN) {
            float4 v = make_float4(acc[ri][0], acc[ri][1], acc[ri][2], acc[ri][3]);
            *(float4*)(out + (size_t)grow * DD + tx * 4) = v;
        }
    }
}

// ---------------------------------------------------------------------------
// rel_out = rel_repr @ w_rel   (tiny)
// ---------------------------------------------------------------------------
__global__ void k_rel(const float* __restrict__ rel,
                      const float* __restrict__ wr,
                      float* __restrict__ out) {
    __shared__ float sR[4][DD];
    int tid = threadIdx.x;
    int j = tid & 63, ry = tid >> 6;
    int r0 = blockIdx.x * 4;
    int grow = r0 + ry;
    sR[ry][j] = (grow < NR) ? rel[(size_t)grow * DD + j] : 0.f;
    __syncthreads();
    float acc = 0.f;
#pragma unroll 8
    for (int k = 0; k < DD; k++) acc += sR[ry][k] * __ldg(&wr[k * DD + j]);
    if (grow < NR) out[(size_t)grow * DD + j] = acc;
}

// ---------------------------------------------------------------------------
extern "C" void kernel_launch(void* const* d_in, const int* in_sizes, int n_in,
                              void* d_out, int out_size) {
    const float* x       = (const float*)d_in[0];
    const float* rel     = (const float*)d_in[1];
    const float* tm      = (const float*)d_in[2];
    const int*   src     = (const int*)d_in[3];
    const int*   dst     = (const int*)d_in[4];
    const int*   ety     = (const int*)d_in[5];
    const int*   eti     = (const int*)d_in[6];
    const float* trans_w = (const float*)d_in[7];
    const float* loop_w  = (const float*)d_in[8];
    const float* w_rel   = (const float*)d_in[9];
    const float* ah      = (const float*)d_in[10];
    const float* at      = (const float*)d_in[11];
    const float* ar      = (const float*)d_in[12];
    const float* ats     = (const float*)d_in[13];

    float* out   = (float*)d_out;            // x_out  [50000*64]
    float* out_r = out + (size_t)NN * DD;    // rel_out [500*64]

    k_zero<<<NB_SCAN, 256>>>();

    {
        int warps = NN + NR + NT;
        int blocks = (warps * 32 + 255) / 256;
        k_scalar<<<blocks, 256>>>(x, rel, tm, ah, at, ar, ats);
    }

    k_hist<<<(NE + 255) / 256, 256>>>(dst);
    k_scan1<<<NB_SCAN, 256>>>();
    k_scan2<<<1, 256>>>();
    k_scan3<<<NB_SCAN, 256>>>();

    k_edge1<<<(NE + 255) / 256, 256>>>(src, dst, ety, eti);

    k_agg<<<(NN * 32 + 255) / 256, 256>>>(x, rel, tm);

    k_gemm<<<(NN + 63) / 64, 256>>>(x, trans_w, loop_w, out);
    k_rel<<<(NR + 3) / 4, 256>>>(rel, w_rel, out_r);

    (void)in_sizes; (void)n_in; (void)out_size;
}